// round 5
// baseline (speedup 1.0000x reference)
#include <cuda_runtime.h>
#include <cuda_bf16.h>
#include <cstdint>
#include <math.h>

#define BSZ   1024
#define TSEQ  64
#define IDIM  64
#define HDIM  1024
#define FUT   16
#define NSTEP (TSEQ + FUT)          // 80
#define G4H   (4 * HDIM)            // 4096
#define OUT_STRIDE (NSTEP * IDIM)   // 5120
#define QMAX  32512                 // 127*256 fixed-point full scale
#define SH    (1.0f / 32512.0f)     // h scale
#define SFB   (4.0f / 32512.0f)     // feedback scale (|out| < 4 assumed, clamped)

typedef int8_t s8;

// ---------------- device scratch ----------------
__device__ float g_xw[(size_t)NSTEP * BSZ * G4H];        // 1.34 GB: per-step x/fb @ W_ih1^T + b1 (gate-permuted)
__device__ s8 g_whh1q1[G4H * HDIM], g_whh1q0[G4H * HDIM];
__device__ s8 g_wih2q1[G4H * HDIM], g_wih2q0[G4H * HDIM];
__device__ s8 g_whh2q1[G4H * HDIM], g_whh2q0[G4H * HDIM];
__device__ s8 g_wih1q1[G4H * 128],  g_wih1q0[G4H * 128]; // K padded 64->128
__device__ s8 g_xq1[BSZ * TSEQ * 128], g_xq0[BSZ * TSEQ * 128]; // padded
__device__ s8 g_h1q1[2][BSZ * HDIM], g_h1q0[2][BSZ * HDIM];
__device__ s8 g_h2q1[2][BSZ * HDIM], g_h2q0[2][BSZ * HDIM];
__device__ s8 g_fbq1[BSZ * 128], g_fbq0[BSZ * 128];      // padded feedback
__device__ float g_c1[BSZ * HDIM], g_c2[BSZ * HDIM];
__device__ float g_bias1[G4H], g_bias2[G4H];
__device__ unsigned g_maxbits[4];     // 0:x 1:whh1 2:w2(common) 3:wih1
__device__ float g_coef[8];           // 0-3: inv quant scales; 4-7: epilogue k for modes 0..3
__device__ float g_part[8 * BSZ * IDIM];

// ---------------- PTX helpers ----------------
__device__ __forceinline__ uint32_t smem_u32(const void* p) {
    return (uint32_t)__cvta_generic_to_shared(p);
}
__device__ __forceinline__ void cp16(uint32_t dst, const void* src) {
    asm volatile("cp.async.cg.shared.global [%0], [%1], 16;\n" :: "r"(dst), "l"(src));
}
__device__ __forceinline__ void cp_commit() { asm volatile("cp.async.commit_group;\n"); }
template<int N> __device__ __forceinline__ void cp_wait() {
    asm volatile("cp.async.wait_group %0;\n" :: "n"(N));
}
__device__ __forceinline__ void ldsm4(uint32_t* r, uint32_t a) {
    asm volatile("ldmatrix.sync.aligned.m8n8.x4.shared.b16 {%0,%1,%2,%3}, [%4];"
        : "=r"(r[0]), "=r"(r[1]), "=r"(r[2]), "=r"(r[3]) : "r"(a));
}
__device__ __forceinline__ void imma16832(int* d, const uint32_t* a, uint32_t b0, uint32_t b1) {
    asm volatile("mma.sync.aligned.m16n8k32.row.col.s32.s8.s8.s32 "
        "{%0,%1,%2,%3}, {%4,%5,%6,%7}, {%8,%9}, {%0,%1,%2,%3};"
        : "+r"(d[0]), "+r"(d[1]), "+r"(d[2]), "+r"(d[3])
        : "r"(a[0]), "r"(a[1]), "r"(a[2]), "r"(a[3]), "r"(b0), "r"(b1));
}
#define SWZ(x) ((x) ^ (((x) >> 3) & 0x70))

__device__ __forceinline__ float sigm(float x) { return 1.f / (1.f + __expf(-x)); }
__device__ __forceinline__ float tanh_f(float x) { return 2.f / (1.f + __expf(-2.f * x)) - 1.f; }
__device__ __forceinline__ void quant2(float v, float invs, s8& a1, s8& a0) {
    int vi = __float2int_rn(v * invs);
    vi = max(-QMAX, min(QMAX, vi));
    int h = (vi + 128) >> 8;
    a1 = (s8)h; a0 = (s8)(vi - (h << 8));
}

// ---------------- prepass kernels ----------------
__global__ void zero_scales() {
    if (threadIdx.x < 4) g_maxbits[threadIdx.x] = 0u;
}
__global__ void maxabs(const float* __restrict__ p, int n, int slot) {
    float m = 0.f;
    for (int i = blockIdx.x * blockDim.x + threadIdx.x; i < n; i += gridDim.x * blockDim.x)
        m = fmaxf(m, fabsf(p[i]));
    #pragma unroll
    for (int o = 16; o > 0; o >>= 1)
        m = fmaxf(m, __shfl_xor_sync(0xFFFFFFFFu, m, o));
    if ((threadIdx.x & 31) == 0)
        atomicMax(&g_maxbits[slot], __float_as_uint(m));
}
__global__ void make_coef() {
    float mx   = __uint_as_float(g_maxbits[0]);
    float mw1  = __uint_as_float(g_maxbits[1]);
    float mw2  = __uint_as_float(g_maxbits[2]);
    float mwi1 = __uint_as_float(g_maxbits[3]);
    g_coef[0] = (float)QMAX / mx;
    g_coef[1] = (float)QMAX / mw1;
    g_coef[2] = (float)QMAX / mw2;
    g_coef[3] = (float)QMAX / mwi1;
    const float q2i = 1.0f / ((float)QMAX * (float)QMAX);
    g_coef[4] = 256.f * mw1 * q2i;             // layer1: s_whh1 * s_h * 256
    g_coef[5] = 256.f * mw2 * q2i;             // layer2
    g_coef[6] = 256.f * mwi1 * 4.f * q2i;      // fb @ wih1
    g_coef[7] = 256.f * mwi1 * mx * q2i;       // x @ wih1
}
// permuted 2-limb weight quantization; dst [4096][KP], src [4096][K] (src row n -> dst row (u<<2)|g)
__global__ void quant_w(const float* __restrict__ src, s8* __restrict__ d1, s8* __restrict__ d0,
                        int K, int KP, const float* __restrict__ invsp) {
    int i = blockIdx.x * blockDim.x + threadIdx.x;
    if (i >= G4H * KP) return;
    int pn = i / KP, k = i % KP;
    int u = pn >> 2, g = pn & 3;
    int n = g * 1024 + u;
    s8 a1 = 0, a0 = 0;
    if (k < K) quant2(src[(size_t)n * K + k], *invsp, a1, a0);
    d1[i] = a1; d0[i] = a0;
}
__global__ void quant_x(const float* __restrict__ x, const float* __restrict__ invsp) {
    int i = blockIdx.x * blockDim.x + threadIdx.x;   // over BSZ*TSEQ*128
    int row = i >> 7, k = i & 127;
    s8 a1 = 0, a0 = 0;
    if (k < IDIM) quant2(x[(size_t)row * IDIM + k], *invsp, a1, a0);
    g_xq1[i] = a1; g_xq0[i] = a0;
}
__global__ void prep_bias(const float* b1a, const float* b1b,
                          const float* b2a, const float* b2b) {
    int n = blockIdx.x * blockDim.x + threadIdx.x;
    int pn = ((n & 1023) << 2) | (n >> 10);
    g_bias1[pn] = b1a[n] + b1b[n];
    g_bias2[pn] = b2a[n] + b2b[n];
}
__global__ void init_state() {
    int i = blockIdx.x * blockDim.x + threadIdx.x;   // over BSZ*HDIM
    g_h1q1[0][i] = 0; g_h1q0[0][i] = 0;
    g_h2q1[0][i] = 0; g_h2q0[0][i] = 0;
    g_c1[i] = 0.f; g_c2[i] = 0.f;
    if (i < BSZ * 128) { g_fbq1[i] = 0; g_fbq0[i] = 0; }
}

// ---------------- unified int8 2-limb GEMM kernel ----------------
// MODE 0: layer1  (A = h1_prev, W = whh1, 8 chunks)  epi: + xw[s] -> LSTM -> h1,c1
// MODE 1: layer2  (A = h1_new|h2_prev, W = wih2|whh2, 16 chunks) epi: + bias2 -> LSTM -> h2,c2
// MODE 2: fb GEMM (A = fb, W = wih1 padded, 1 chunk) epi: + bias1 -> fp32 xw[s+1]
// MODE 3: x GEMM  (A = x rows, W = wih1, 1 chunk, M = B*T) epi: + bias1 -> fp32 xw[t] (remapped)
#define STAGE 65536   // A1 16K | A0 16K | W1 16K | W0 16K

template<int MODE>
__global__ void __launch_bounds__(256, 1)
ilstm(const s8* __restrict__ A1a, const s8* __restrict__ A0a, int sA,
      const s8* __restrict__ A1b, const s8* __restrict__ A0b, int sB,
      const s8* __restrict__ W1a, const s8* __restrict__ W0a, int sWa,
      const s8* __restrict__ W1b, const s8* __restrict__ W0b, int sWb,
      const float* __restrict__ coefp, const float* __restrict__ aux,
      float* __restrict__ cbuf, s8* __restrict__ Hq1, s8* __restrict__ Hq0,
      float* __restrict__ fdst)
{
    constexpr int C  = (MODE == 1) ? 16 : ((MODE == 0) ? 8 : 1);
    constexpr int nA = (MODE == 1) ? 8 : C;

    extern __shared__ __align__(1024) char smem[];
    const uint32_t sb = smem_u32(smem);
    const int tid = threadIdx.x;
    const size_t mBase = (size_t)blockIdx.y * 128;
    const int nBase = blockIdx.x * 128;

    float* sbias = (float*)(smem + 3 * STAGE);
    if (MODE != 0) { if (tid < 128) sbias[tid] = aux[nBase + tid]; }

    auto load_chunk = [&](int c, int st) {
        const s8 *A1, *A0, *W1, *W0; int as, ws;
        if (c < nA) { A1 = A1a + c * 128; A0 = A0a + c * 128; as = sA;
                      W1 = W1a + c * 128; W0 = W0a + c * 128; ws = sWa; }
        else        { int d = c - nA;
                      A1 = A1b + d * 128; A0 = A0b + d * 128; as = sB;
                      W1 = W1b + d * 128; W0 = W0b + d * 128; ws = sWb; }
        uint32_t base = sb + st * STAGE;
        #pragma unroll
        for (int j = 0; j < 4; ++j) {
            int o = tid + j * 256; int row = o >> 3; int cb = (o & 7) * 16;
            uint32_t boff = SWZ((uint32_t)(row * 128 + cb));
            cp16(base + boff,         A1 + (mBase + row) * (size_t)as + cb);
            cp16(base + 16384 + boff, A0 + (mBase + row) * (size_t)as + cb);
            cp16(base + 32768 + boff, W1 + (size_t)(nBase + row) * ws + cb);
            cp16(base + 49152 + boff, W0 + (size_t)(nBase + row) * ws + cb);
        }
        cp_commit();
    };

    const int w = tid >> 5, l = tid & 31;
    const int wm = (w & 3) * 32, wn = (w >> 2) * 64;

    int ahi[2][8][4] = {};
    int amd[2][8][4] = {};

    load_chunk(0, 0);
    if (C > 1) load_chunk(1, 1); else cp_commit();
    if (C > 2) load_chunk(2, 2); else cp_commit();

    const int aRowOff[2] = { (wm + 0 * 16 + (l & 15)) << 7, (wm + 1 * 16 + (l & 15)) << 7 };
    const int aColSub = (l >> 4) << 4;
    int wRowOff[4];
    #pragma unroll
    for (int ng = 0; ng < 4; ++ng)
        wRowOff[ng] = (wn + ng * 16 + (l & 7) + (((l >> 4) & 1) << 3)) << 7;
    const int wColSub = ((l >> 3) & 1) << 4;

    for (int c = 0; c < C; ++c) {
        const int st = c % 3;
        cp_wait<2>();
        __syncthreads();

        const uint32_t bA1 = sb + st * STAGE;
        const uint32_t bA0 = bA1 + 16384;
        const uint32_t bW1 = bA1 + 32768;
        const uint32_t bW0 = bA1 + 49152;

        #pragma unroll
        for (int ks = 0; ks < 4; ++ks) {
            uint32_t a1[2][4], a0[2][4], w1[4][4], w0[4][4];
            #pragma unroll
            for (int mt = 0; mt < 2; ++mt) {
                uint32_t off = SWZ((uint32_t)(aRowOff[mt] + ks * 32 + aColSub));
                ldsm4(a1[mt], bA1 + off);
                ldsm4(a0[mt], bA0 + off);
            }
            #pragma unroll
            for (int ng = 0; ng < 4; ++ng) {
                uint32_t off = SWZ((uint32_t)(wRowOff[ng] + ks * 32 + wColSub));
                ldsm4(w1[ng], bW1 + off);
                ldsm4(w0[ng], bW0 + off);
            }
            #pragma unroll
            for (int mt = 0; mt < 2; ++mt) {
                #pragma unroll
                for (int ng = 0; ng < 4; ++ng) {
                    imma16832(ahi[mt][ng * 2],     a1[mt], w1[ng][0], w1[ng][1]);
                    imma16832(amd[mt][ng * 2],     a1[mt], w0[ng][0], w0[ng][1]);
                    imma16832(amd[mt][ng * 2],     a0[mt], w1[ng][0], w1[ng][1]);
                    imma16832(ahi[mt][ng * 2 + 1], a1[mt], w1[ng][2], w1[ng][3]);
                    imma16832(amd[mt][ng * 2 + 1], a1[mt], w0[ng][2], w0[ng][3]);
                    imma16832(amd[mt][ng * 2 + 1], a0[mt], w1[ng][2], w1[ng][3]);
                }
            }
        }
        __syncthreads();
        if (c + 3 < C) load_chunk(c + 3, (c + 3) % 3);
        else cp_commit();
    }

    // ---------------- epilogue ----------------
    const float kk = *coefp;
    const int gr = l >> 2;
    const bool odd = l & 1;
    const int q = (l >> 1) & 1;

    if (MODE <= 1) {
        #pragma unroll
        for (int mt = 0; mt < 2; ++mt) {
            #pragma unroll
            for (int nt = 0; nt < 8; ++nt) {
                float c0 = kk * (256.f * (float)ahi[mt][nt][0] + (float)amd[mt][nt][0]);
                float c1 = kk * (256.f * (float)ahi[mt][nt][1] + (float)amd[mt][nt][1]);
                float c2 = kk * (256.f * (float)ahi[mt][nt][2] + (float)amd[mt][nt][2]);
                float c3 = kk * (256.f * (float)ahi[mt][nt][3] + (float)amd[mt][nt][3]);
                float sx = odd ? c0 : c2;
                float sy = odd ? c1 : c3;
                float rx = __shfl_xor_sync(0xFFFFFFFFu, sx, 1);
                float ry = __shfl_xor_sync(0xFFFFFFFFu, sy, 1);
                float iv, fv, gv, ov;
                if (!odd) { iv = c0; fv = c1; gv = rx; ov = ry; }
                else      { iv = rx; fv = ry; gv = c2; ov = c3; }
                int nn  = wn + nt * 8 + q * 4;
                int row = (int)mBase + wm + mt * 16 + gr + (odd ? 8 : 0);
                float bi, bf, bg, bo;
                if (MODE == 0) {
                    float4 xv = *(const float4*)(aux + (size_t)row * G4H + nBase + nn);
                    bi = xv.x; bf = xv.y; bg = xv.z; bo = xv.w;
                } else {
                    bi = sbias[nn]; bf = sbias[nn + 1]; bg = sbias[nn + 2]; bo = sbias[nn + 3];
                }
                float gi = sigm(iv + bi), gf = sigm(fv + bf);
                float gg = tanh_f(gv + bg), go = sigm(ov + bo);
                int unit = (nBase + nn) >> 2;
                size_t idx = (size_t)row * HDIM + unit;
                float cn = gf * cbuf[idx] + gi * gg;
                cbuf[idx] = cn;
                float hn = go * tanh_f(cn);
                int vi2 = __float2int_rn(hn * (float)QMAX);
                int hh = (vi2 + 128) >> 8;
                Hq1[idx] = (s8)hh; Hq0[idx] = (s8)(vi2 - (hh << 8));
            }
        }
    } else {
        #pragma unroll
        for (int mt = 0; mt < 2; ++mt) {
            #pragma unroll
            for (int nt = 0; nt < 8; ++nt) {
                int lc_ = wn + nt * 8 + 2 * (l & 3);
                float v0 = kk * (256.f * (float)ahi[mt][nt][0] + (float)amd[mt][nt][0]) + sbias[lc_];
                float v1 = kk * (256.f * (float)ahi[mt][nt][1] + (float)amd[mt][nt][1]) + sbias[lc_ + 1];
                float v2 = kk * (256.f * (float)ahi[mt][nt][2] + (float)amd[mt][nt][2]) + sbias[lc_];
                float v3 = kk * (256.f * (float)ahi[mt][nt][3] + (float)amd[mt][nt][3]) + sbias[lc_ + 1];
                size_t r0 = mBase + wm + mt * 16 + (l >> 2);
                size_t r1 = r0 + 8;
                size_t m0 = (MODE == 3) ? ((size_t)(r0 & 63) * BSZ + (r0 >> 6)) : r0;
                size_t m1 = (MODE == 3) ? ((size_t)(r1 & 63) * BSZ + (r1 >> 6)) : r1;
                float* p0 = fdst + m0 * G4H + nBase + lc_;
                float* p1 = fdst + m1 * G4H + nBase + lc_;
                p0[0] = v0; p0[1] = v1;
                p1[0] = v2; p1[1] = v3;
            }
        }
    }
}

// ---------------- head GEMM: out = h2 @ W_lin^T + b_lin ----------------
__global__ __launch_bounds__(256)
void lin_stage1_kernel(const s8* __restrict__ Hq1, const s8* __restrict__ Hq0,
                       const float* __restrict__ Wlin) {
    __shared__ float Hs[16][68];
    __shared__ float Ws[16][68];

    const int tid = threadIdx.x;
    const int mBase = blockIdx.x * 64;
    const int ks = blockIdx.y;
    const int kBeg = ks * 128;

    const int lr = tid >> 2;
    const int lc = (tid & 3) << 2;
    const int tx = tid & 15;
    const int ty = tid >> 4;

    float acc[4][4];
    #pragma unroll
    for (int i = 0; i < 4; ++i)
        #pragma unroll
        for (int j = 0; j < 4; ++j) acc[i][j] = 0.f;

    for (int k0 = kBeg; k0 < kBeg + 128; k0 += 16) {
        size_t hoff = (size_t)(mBase + lr) * HDIM + k0 + lc;
        int p1 = *(const int*)(Hq1 + hoff);
        int p0 = *(const int*)(Hq0 + hoff);
        #pragma unroll
        for (int j = 0; j < 4; ++j) {
            int a1 = (int)((s8)(p1 >> (8 * j)));
            int a0 = (int)((s8)(p0 >> (8 * j)));
            Hs[lc + j][lr] = (float)(a1 * 256 + a0) * SH;
        }
        float4 wv = *reinterpret_cast<const float4*>(&Wlin[(size_t)lr * HDIM + k0 + lc]);
        Ws[lc + 0][lr] = wv.x; Ws[lc + 1][lr] = wv.y;
        Ws[lc + 2][lr] = wv.z; Ws[lc + 3][lr] = wv.w;
        __syncthreads();

        #pragma unroll
        for (int kk = 0; kk < 16; ++kk) {
            float a[4], wv2[4];
            #pragma unroll
            for (int i = 0; i < 4; ++i) a[i] = Hs[kk][ty * 4 + i];
            #pragma unroll
            for (int j = 0; j < 4; ++j) wv2[j] = Ws[kk][tx * 4 + j];
            #pragma unroll
            for (int i = 0; i < 4; ++i)
                #pragma unroll
                for (int j = 0; j < 4; ++j)
                    acc[i][j] = fmaf(a[i], wv2[j], acc[i][j]);
        }
        __syncthreads();
    }

    #pragma unroll
    for (int i = 0; i < 4; ++i) {
        int m = mBase + ty * 4 + i;
        #pragma unroll
        for (int j = 0; j < 4; ++j) {
            int n = tx * 4 + j;
            g_part[(size_t)ks * (BSZ * IDIM) + m * IDIM + n] = acc[i][j];
        }
    }
}

__global__ void lin_stage2_kernel(const float* __restrict__ blin,
                                  float* __restrict__ outp) {
    int idx = blockIdx.x * blockDim.x + threadIdx.x;   // over BSZ*IDIM
    int m = idx >> 6;
    int n = idx & 63;
    float s = blin[n];
    #pragma unroll
    for (int ks = 0; ks < 8; ++ks) s += g_part[ks * (BSZ * IDIM) + idx];
    outp[(size_t)m * OUT_STRIDE + n] = s;
    // quantize feedback with fixed scale SFB = 4/QMAX
    int vi = __float2int_rn(s * ((float)QMAX / 4.f));
    vi = max(-QMAX, min(QMAX, vi));
    int h = (vi + 128) >> 8;
    g_fbq1[m * 128 + n] = (s8)h;
    g_fbq0[m * 128 + n] = (s8)(vi - (h << 8));
}

// ---------------- host launch ----------------
extern "C" void kernel_launch(void* const* d_in, const int* in_sizes, int n_in,
                              void* d_out, int out_size) {
    const float* x     = (const float*)d_in[0];
    const float* W_ih1 = (const float*)d_in[1];
    const float* W_hh1 = (const float*)d_in[2];
    const float* b_ih1 = (const float*)d_in[3];
    const float* b_hh1 = (const float*)d_in[4];
    const float* W_ih2 = (const float*)d_in[5];
    const float* W_hh2 = (const float*)d_in[6];
    const float* b_ih2 = (const float*)d_in[7];
    const float* b_hh2 = (const float*)d_in[8];
    const float* W_lin = (const float*)d_in[9];
    const float* b_lin = (const float*)d_in[10];
    float* out = (float*)d_out;

    void *xw, *whh1q1, *whh1q0, *wih2q1, *wih2q0, *whh2q1, *whh2q0, *wih1q1, *wih1q0;
    void *xq1, *xq0, *h1q1, *h1q0, *h2q1, *h2q0, *fbq1, *fbq0, *c1, *c2, *bias1, *bias2, *coef;
    cudaGetSymbolAddress(&xw, g_xw);
    cudaGetSymbolAddress(&whh1q1, g_whh1q1); cudaGetSymbolAddress(&whh1q0, g_whh1q0);
    cudaGetSymbolAddress(&wih2q1, g_wih2q1); cudaGetSymbolAddress(&wih2q0, g_wih2q0);
    cudaGetSymbolAddress(&whh2q1, g_whh2q1); cudaGetSymbolAddress(&whh2q0, g_whh2q0);
    cudaGetSymbolAddress(&wih1q1, g_wih1q1); cudaGetSymbolAddress(&wih1q0, g_wih1q0);
    cudaGetSymbolAddress(&xq1, g_xq1);       cudaGetSymbolAddress(&xq0, g_xq0);
    cudaGetSymbolAddress(&h1q1, g_h1q1);     cudaGetSymbolAddress(&h1q0, g_h1q0);
    cudaGetSymbolAddress(&h2q1, g_h2q1);     cudaGetSymbolAddress(&h2q0, g_h2q0);
    cudaGetSymbolAddress(&fbq1, g_fbq1);     cudaGetSymbolAddress(&fbq0, g_fbq0);
    cudaGetSymbolAddress(&c1, g_c1);         cudaGetSymbolAddress(&c2, g_c2);
    cudaGetSymbolAddress(&bias1, g_bias1);   cudaGetSymbolAddress(&bias2, g_bias2);
    cudaGetSymbolAddress(&coef, g_coef);

    s8* H1q1[2] = { (s8*)h1q1, (s8*)h1q1 + BSZ * HDIM };
    s8* H1q0[2] = { (s8*)h1q0, (s8*)h1q0 + BSZ * HDIM };
    s8* H2q1[2] = { (s8*)h2q1, (s8*)h2q1 + BSZ * HDIM };
    s8* H2q0[2] = { (s8*)h2q0, (s8*)h2q0 + BSZ * HDIM };
    const float* coeff = (const float*)coef;
    float* xwf = (float*)xw;

    constexpr int SMEM_MAIN = 3 * STAGE + 512;   // 197120
    cudaFuncSetAttribute(ilstm<0>, cudaFuncAttributeMaxDynamicSharedMemorySize, SMEM_MAIN);
    cudaFuncSetAttribute(ilstm<1>, cudaFuncAttributeMaxDynamicSharedMemorySize, SMEM_MAIN);
    cudaFuncSetAttribute(ilstm<2>, cudaFuncAttributeMaxDynamicSharedMemorySize, SMEM_MAIN);
    cudaFuncSetAttribute(ilstm<3>, cudaFuncAttributeMaxDynamicSharedMemorySize, SMEM_MAIN);

    // ---- prepasses ----
    zero_scales<<<1, 32>>>();
    maxabs<<<256, 256>>>(x, BSZ * TSEQ * IDIM, 0);
    maxabs<<<256, 256>>>(W_hh1, G4H * HDIM, 1);
    maxabs<<<256, 256>>>(W_ih2, G4H * HDIM, 2);
    maxabs<<<256, 256>>>(W_hh2, G4H * HDIM, 2);
    maxabs<<<64, 256>>>(W_ih1, G4H * IDIM, 3);
    make_coef<<<1, 1>>>();
    quant_w<<<(G4H * 1024) / 256, 256>>>(W_hh1, (s8*)whh1q1, (s8*)whh1q0, 1024, 1024, coeff + 1);
    quant_w<<<(G4H * 1024) / 256, 256>>>(W_ih2, (s8*)wih2q1, (s8*)wih2q0, 1024, 1024, coeff + 2);
    quant_w<<<(G4H * 1024) / 256, 256>>>(W_hh2, (s8*)whh2q1, (s8*)whh2q0, 1024, 1024, coeff + 2);
    quant_w<<<(G4H * 128) / 256, 256>>>(W_ih1, (s8*)wih1q1, (s8*)wih1q0, 64, 128, coeff + 3);
    quant_x<<<(BSZ * TSEQ * 128) / 256, 256>>>(x, coeff + 0);
    prep_bias<<<16, 256>>>(b_ih1, b_hh1, b_ih2, b_hh2);
    init_state<<<4096, 256>>>();

    // XW prepass: all 64 timesteps' x @ W_ih1^T + b1, permuted, into g_xw[0..63]
    ilstm<3><<<dim3(32, 512), 256, SMEM_MAIN>>>(
        (const s8*)xq1, (const s8*)xq0, 128,
        nullptr, nullptr, 0,
        (const s8*)wih1q1, (const s8*)wih1q0, 128,
        nullptr, nullptr, 0,
        coeff + 7, (const float*)bias1,
        nullptr, nullptr, nullptr, xwf);

    const dim3 gL(32, 8);

    for (int s = 0; s < NSTEP; ++s) {
        int rp = s & 1, wp = rp ^ 1;

        // layer 1: h1_prev @ whh1 (+ xw[s], fused LSTM)
        ilstm<0><<<gL, 256, SMEM_MAIN>>>(
            H1q1[rp], H1q0[rp], HDIM,
            nullptr, nullptr, 0,
            (const s8*)whh1q1, (const s8*)whh1q0, HDIM,
            nullptr, nullptr, 0,
            coeff + 4, xwf + (size_t)s * BSZ * G4H,
            (float*)c1, H1q1[wp], H1q0[wp], nullptr);

        // layer 2: (h1_new | h2_prev) @ (wih2 | whh2) + bias2
        ilstm<1><<<gL, 256, SMEM_MAIN>>>(
            H1q1[wp], H1q0[wp], HDIM,
            H2q1[rp], H2q0[rp], HDIM,
            (const s8*)wih2q1, (const s8*)wih2q0, HDIM,
            (const s8*)whh2q1, (const s8*)whh2q0, HDIM,
            coeff + 5, (const float*)bias2,
            (float*)c2, H2q1[wp], H2q0[wp], nullptr);

        // head
        lin_stage1_kernel<<<dim3(BSZ / 64, 8), 256>>>(H2q1[wp], H2q0[wp], W_lin);
        lin_stage2_kernel<<<(BSZ * IDIM) / 256, 256>>>(b_lin, out + (size_t)s * IDIM);

        // feedback GEMM: fb @ wih1 + b1 -> xw[s+1] (future steps only)
        if (s >= TSEQ - 1 && s < NSTEP - 1) {
            ilstm<2><<<gL, 256, SMEM_MAIN>>>(
                (const s8*)fbq1, (const s8*)fbq0, 128,
                nullptr, nullptr, 0,
                (const s8*)wih1q1, (const s8*)wih1q0, 128,
                nullptr, nullptr, 0,
                coeff + 6, (const float*)bias1,
                nullptr, nullptr, nullptr, xwf + (size_t)(s + 1) * BSZ * G4H);
        }
    }
}

// round 6
// speedup vs baseline: 5.7310x; 5.7310x over previous
#include <cuda_runtime.h>
#include <cuda_fp16.h>
#include <cstdint>
#include <math.h>

#define BSZ   1024
#define TSEQ  64
#define IDIM  64
#define HDIM  1024
#define FUT   16
#define NSTEP (TSEQ + FUT)          // 80
#define G4H   (4 * HDIM)            // 4096
#define OUT_STRIDE (NSTEP * IDIM)   // 5120

typedef __half f16;

// ---------------- device scratch (static; no runtime allocation) ----------------
__device__ f16 g_wih1[G4H * IDIM];
__device__ f16 g_whh1[G4H * HDIM];
__device__ f16 g_wih2[G4H * HDIM];
__device__ f16 g_whh2[G4H * HDIM];
__device__ float g_bias1[G4H], g_bias2[G4H];
__device__ f16 g_x[BSZ * TSEQ * IDIM];
__device__ f16 g_h1[2][BSZ * HDIM];
__device__ f16 g_h2[2][BSZ * HDIM];
__device__ float g_c1[BSZ * HDIM], g_c2[BSZ * HDIM];
__device__ f16 g_fb[BSZ * IDIM];              // autoregressive feedback
__device__ float g_part[8 * BSZ * IDIM];      // head split-K partials

// ---------------- helpers ----------------
__device__ __forceinline__ uint32_t smem_u32(const void* p) {
    return (uint32_t)__cvta_generic_to_shared(p);
}
__device__ __forceinline__ void cp16(uint32_t dst, const void* src) {
    asm volatile("cp.async.cg.shared.global [%0], [%1], 16;\n" :: "r"(dst), "l"(src));
}
__device__ __forceinline__ void cp_commit() { asm volatile("cp.async.commit_group;\n"); }
template<int N> __device__ __forceinline__ void cp_wait() {
    asm volatile("cp.async.wait_group %0;\n" :: "n"(N));
}
__device__ __forceinline__ void ldsm4(uint32_t* r, uint32_t a) {
    asm volatile("ldmatrix.sync.aligned.m8n8.x4.shared.b16 {%0,%1,%2,%3}, [%4];"
        : "=r"(r[0]), "=r"(r[1]), "=r"(r[2]), "=r"(r[3]) : "r"(a));
}
__device__ __forceinline__ void mma16816(float* d, const uint32_t* a, uint32_t b0, uint32_t b1) {
    asm volatile("mma.sync.aligned.m16n8k16.row.col.f32.f16.f16.f32 "
        "{%0,%1,%2,%3}, {%4,%5,%6,%7}, {%8,%9}, {%0,%1,%2,%3};"
        : "+f"(d[0]), "+f"(d[1]), "+f"(d[2]), "+f"(d[3])
        : "r"(a[0]), "r"(a[1]), "r"(a[2]), "r"(a[3]), "r"(b0), "r"(b1));
}
#define SWZ(x) ((x) ^ (((x) >> 3) & 0x70))

__device__ __forceinline__ float sigm(float x) { return 1.f / (1.f + __expf(-x)); }
__device__ __forceinline__ float tanh_f(float x) { return 2.f / (1.f + __expf(-2.f * x)) - 1.f; }

// ---------------- prepass kernels ----------------
// Gate-permuting weight convert: row n (gate g = n/1024, unit u = n%1024) -> row u*4+g
__global__ void prep_w_perm(const float* __restrict__ src, f16* __restrict__ dst, int K) {
    size_t e = ((size_t)blockIdx.x * blockDim.x + threadIdx.x) * 4;
    int n = (int)(e / K);
    int k = (int)(e % K);
    int pn = ((n & 1023) << 2) | (n >> 10);
    float4 v = *(const float4*)(src + e);
    dst[(size_t)pn * K + k + 0] = __float2half(v.x);
    dst[(size_t)pn * K + k + 1] = __float2half(v.y);
    dst[(size_t)pn * K + k + 2] = __float2half(v.z);
    dst[(size_t)pn * K + k + 3] = __float2half(v.w);
}
__global__ void prep_half(const float* __restrict__ src, f16* __restrict__ dst) {
    size_t e = ((size_t)blockIdx.x * blockDim.x + threadIdx.x) * 4;
    float4 v = *(const float4*)(src + e);
    dst[e + 0] = __float2half(v.x);
    dst[e + 1] = __float2half(v.y);
    dst[e + 2] = __float2half(v.z);
    dst[e + 3] = __float2half(v.w);
}
__global__ void prep_bias(const float* b1a, const float* b1b,
                          const float* b2a, const float* b2b) {
    int n = blockIdx.x * blockDim.x + threadIdx.x;   // 0..4095
    int pn = ((n & 1023) << 2) | (n >> 10);
    g_bias1[pn] = b1a[n] + b1b[n];
    g_bias2[pn] = b2a[n] + b2b[n];
}
__global__ void init_state() {
    int i = blockIdx.x * blockDim.x + threadIdx.x;   // over BSZ*HDIM
    f16 z = __float2half(0.f);
    g_h1[0][i] = z; g_h2[0][i] = z;
    g_c1[i] = 0.f;  g_c2[i] = 0.f;
}

// ---------------- main LSTM layer kernel (fp16 mma.sync, single term) ----------------
// C tile 128(M) x 128(N gate cols). Two A phases: nA chunks of (A1,W1), nB of (A2,W2).
// K-chunk = 64 fp16 (128B rows, SW128 swizzle). Fused LSTM epilogue.
#define STAGE 32768   // A 16K | W 16K

__global__ void __launch_bounds__(256, 2)
gemm_lstm(const f16* __restrict__ A1, int s1, int nA,
          const f16* __restrict__ A2, int s2, int nB,
          const f16* __restrict__ W1, int w1s,
          const f16* __restrict__ W2, int w2s,
          const float* __restrict__ bias,
          float* __restrict__ cbuf, f16* __restrict__ H)
{
    extern __shared__ __align__(1024) char smem[];
    const int tid = threadIdx.x;
    const int mBase = blockIdx.y * 128;
    const int nBase = blockIdx.x * 128;
    const uint32_t sb = smem_u32(smem);

    float* sbias = (float*)(smem + 3 * STAGE);
    if (tid < 128) sbias[tid] = bias[nBase + tid];

    const int C = nA + nB;

    auto load_chunk = [&](int c, int st) {
        const f16 *A, *W; int as, ws;
        if (c < nA) { A = A1 + c * 64; as = s1; W = W1 + c * 64; ws = w1s; }
        else        { int d = c - nA;
                      A = A2 + d * 64; as = s2; W = W2 + d * 64; ws = w2s; }
        uint32_t base = sb + st * STAGE;
        #pragma unroll
        for (int j = 0; j < 4; ++j) {
            int o = tid + j * 256; int row = o >> 3; int eo = (o & 7) * 8;
            uint32_t boff = SWZ(row * 128 + eo * 2);
            cp16(base + boff,         A + (size_t)(mBase + row) * as + eo);
            cp16(base + 16384 + boff, W + (size_t)(nBase + row) * ws + eo);
        }
        cp_commit();
    };

    // warp mapping: 8 warps = 4(m) x 2(n); warp tile 32 x 64
    const int w = tid >> 5, l = tid & 31;
    const int wm = (w & 3) * 32, wn = (w >> 2) * 64;

    float acc[2][8][4];
    #pragma unroll
    for (int mt = 0; mt < 2; ++mt)
        #pragma unroll
        for (int nt = 0; nt < 8; ++nt)
            #pragma unroll
            for (int j = 0; j < 4; ++j) acc[mt][nt][j] = 0.f;

    load_chunk(0, 0);
    if (C > 1) load_chunk(1, 1); else cp_commit();
    if (C > 2) load_chunk(2, 2); else cp_commit();

    const int aRowOff[2] = { (wm + 0 * 16 + (l & 15)) << 7, (wm + 1 * 16 + (l & 15)) << 7 };
    const int aColSub = (l >> 4) << 4;                        // 0 or 16
    int wRowOff[4];
    #pragma unroll
    for (int ng = 0; ng < 4; ++ng)
        wRowOff[ng] = (wn + ng * 16 + (l & 7) + (((l >> 4) & 1) << 3)) << 7;
    const int wColSub = ((l >> 3) & 1) << 4;                  // 0 or 16

    for (int c = 0; c < C; ++c) {
        const int st = c % 3;
        cp_wait<2>();
        __syncthreads();

        const uint32_t bA = sb + st * STAGE;
        const uint32_t bW = bA + 16384;

        #pragma unroll
        for (int ks = 0; ks < 4; ++ks) {
            uint32_t af[2][4], wf[4][4];
            #pragma unroll
            for (int mt = 0; mt < 2; ++mt) {
                uint32_t off = SWZ((uint32_t)(aRowOff[mt] + ks * 32 + aColSub));
                ldsm4(af[mt], bA + off);
            }
            #pragma unroll
            for (int ng = 0; ng < 4; ++ng) {
                uint32_t off = SWZ((uint32_t)(wRowOff[ng] + ks * 32 + wColSub));
                ldsm4(wf[ng], bW + off);
            }
            #pragma unroll
            for (int mt = 0; mt < 2; ++mt) {
                #pragma unroll
                for (int ng = 0; ng < 4; ++ng) {
                    mma16816(acc[mt][ng * 2],     af[mt], wf[ng][0], wf[ng][1]);
                    mma16816(acc[mt][ng * 2 + 1], af[mt], wf[ng][2], wf[ng][3]);
                }
            }
        }
        __syncthreads();
        if (c + 3 < C) load_chunk(c + 3, (c + 3) % 3);
        else cp_commit();   // keep group count aligned with wait<2>
    }

    // ---------------- fused LSTM epilogue ----------------
    const int gr = l >> 2;
    const bool odd = l & 1;
    const int q = (l >> 1) & 1;

    #pragma unroll
    for (int mt = 0; mt < 2; ++mt) {
        #pragma unroll
        for (int nt = 0; nt < 8; ++nt) {
            float c0 = acc[mt][nt][0], c1 = acc[mt][nt][1];
            float c2 = acc[mt][nt][2], c3 = acc[mt][nt][3];
            float sx = odd ? c0 : c2;
            float sy = odd ? c1 : c3;
            float rx = __shfl_xor_sync(0xFFFFFFFFu, sx, 1);
            float ry = __shfl_xor_sync(0xFFFFFFFFu, sy, 1);
            float iv, fv, gv, ov;
            if (!odd) { iv = c0; fv = c1; gv = rx; ov = ry; }
            else      { iv = rx; fv = ry; gv = c2; ov = c3; }
            int nn  = wn + nt * 8 + q * 4;           // CTA-local gate-i column
            int row = mBase + wm + mt * 16 + gr + (odd ? 8 : 0);
            float xi = iv + sbias[nn + 0];
            float xf = fv + sbias[nn + 1];
            float xg = gv + sbias[nn + 2];
            float xo = ov + sbias[nn + 3];
            float gi = sigm(xi), gf = sigm(xf), gg = tanh_f(xg), go = sigm(xo);
            int unit = (nBase + nn) >> 2;
            size_t idx = (size_t)row * HDIM + unit;
            float cn = gf * cbuf[idx] + gi * gg;
            cbuf[idx] = cn;
            float hn = go * tanh_f(cn);
            H[idx] = __float2half(hn);
        }
    }
}

// ---------------- head GEMM: out = h2 @ W_lin^T + b_lin (fp32 split-K) ----------------
__global__ __launch_bounds__(256)
void lin_stage1_kernel(const f16* __restrict__ H, const float* __restrict__ Wlin) {
    __shared__ float Hs[16][68];
    __shared__ float Ws[16][68];

    const int tid = threadIdx.x;
    const int mBase = blockIdx.x * 64;
    const int ks = blockIdx.y;               // 0..7
    const int kBeg = ks * 128;

    const int lr = tid >> 2;
    const int lc = (tid & 3) << 2;
    const int tx = tid & 15;
    const int ty = tid >> 4;

    float acc[4][4];
    #pragma unroll
    for (int i = 0; i < 4; ++i)
        #pragma unroll
        for (int j = 0; j < 4; ++j) acc[i][j] = 0.f;

    for (int k0 = kBeg; k0 < kBeg + 128; k0 += 16) {
        size_t hoff = (size_t)(mBase + lr) * HDIM + k0 + lc;
        const __half2* ph = (const __half2*)(H + hoff);
        float2 h0 = __half22float2(ph[0]);
        float2 h1 = __half22float2(ph[1]);
        Hs[lc + 0][lr] = h0.x; Hs[lc + 1][lr] = h0.y;
        Hs[lc + 2][lr] = h1.x; Hs[lc + 3][lr] = h1.y;
        float4 wv = *reinterpret_cast<const float4*>(&Wlin[(size_t)lr * HDIM + k0 + lc]);
        Ws[lc + 0][lr] = wv.x; Ws[lc + 1][lr] = wv.y;
        Ws[lc + 2][lr] = wv.z; Ws[lc + 3][lr] = wv.w;
        __syncthreads();

        #pragma unroll
        for (int kk = 0; kk < 16; ++kk) {
            float a[4], wv2[4];
            #pragma unroll
            for (int i = 0; i < 4; ++i) a[i] = Hs[kk][ty * 4 + i];
            #pragma unroll
            for (int j = 0; j < 4; ++j) wv2[j] = Ws[kk][tx * 4 + j];
            #pragma unroll
            for (int i = 0; i < 4; ++i)
                #pragma unroll
                for (int j = 0; j < 4; ++j)
                    acc[i][j] = fmaf(a[i], wv2[j], acc[i][j]);
        }
        __syncthreads();
    }

    #pragma unroll
    for (int i = 0; i < 4; ++i) {
        int m = mBase + ty * 4 + i;
        #pragma unroll
        for (int j = 0; j < 4; ++j) {
            int n = tx * 4 + j;
            g_part[(size_t)ks * (BSZ * IDIM) + m * IDIM + n] = acc[i][j];
        }
    }
}

__global__ void lin_stage2_kernel(const float* __restrict__ blin,
                                  float* __restrict__ outp) {
    int idx = blockIdx.x * blockDim.x + threadIdx.x;   // over BSZ*IDIM
    int m = idx >> 6;
    int n = idx & 63;
    float s = blin[n];
    #pragma unroll
    for (int ks = 0; ks < 8; ++ks) s += g_part[ks * (BSZ * IDIM) + idx];
    outp[(size_t)m * OUT_STRIDE + n] = s;
    g_fb[idx] = __float2half(s);
}

// ---------------- host launch ----------------
extern "C" void kernel_launch(void* const* d_in, const int* in_sizes, int n_in,
                              void* d_out, int out_size) {
    const float* x     = (const float*)d_in[0];
    const float* W_ih1 = (const float*)d_in[1];
    const float* W_hh1 = (const float*)d_in[2];
    const float* b_ih1 = (const float*)d_in[3];
    const float* b_hh1 = (const float*)d_in[4];
    const float* W_ih2 = (const float*)d_in[5];
    const float* W_hh2 = (const float*)d_in[6];
    const float* b_ih2 = (const float*)d_in[7];
    const float* b_hh2 = (const float*)d_in[8];
    const float* W_lin = (const float*)d_in[9];
    const float* b_lin = (const float*)d_in[10];
    float* out = (float*)d_out;

    void *wih1, *whh1, *wih2, *whh2, *xh, *h1, *h2, *c1, *c2, *fb, *bias1, *bias2;
    cudaGetSymbolAddress(&wih1, g_wih1);   cudaGetSymbolAddress(&whh1, g_whh1);
    cudaGetSymbolAddress(&wih2, g_wih2);   cudaGetSymbolAddress(&whh2, g_whh2);
    cudaGetSymbolAddress(&xh, g_x);
    cudaGetSymbolAddress(&h1, g_h1);       cudaGetSymbolAddress(&h2, g_h2);
    cudaGetSymbolAddress(&c1, g_c1);       cudaGetSymbolAddress(&c2, g_c2);
    cudaGetSymbolAddress(&fb, g_fb);
    cudaGetSymbolAddress(&bias1, g_bias1); cudaGetSymbolAddress(&bias2, g_bias2);

    f16* H1[2] = { (f16*)h1, (f16*)h1 + BSZ * HDIM };
    f16* H2[2] = { (f16*)h2, (f16*)h2 + BSZ * HDIM };

    constexpr int SMEM_MAIN = 3 * STAGE + 512;   // 98816
    cudaFuncSetAttribute(gemm_lstm, cudaFuncAttributeMaxDynamicSharedMemorySize, SMEM_MAIN);

    // ---- prepasses ----
    prep_w_perm<<<4096, 256>>>(W_hh1, (f16*)whh1, HDIM);
    prep_w_perm<<<4096, 256>>>(W_ih2, (f16*)wih2, HDIM);
    prep_w_perm<<<4096, 256>>>(W_hh2, (f16*)whh2, HDIM);
    prep_w_perm<<<256, 256>>>(W_ih1, (f16*)wih1, IDIM);
    prep_half<<<4096, 256>>>(x, (f16*)xh);
    prep_bias<<<16, 256>>>(b_ih1, b_hh1, b_ih2, b_hh2);
    init_state<<<4096, 256>>>();

    const dim3 gL(G4H / 128, BSZ / 128);   // (32, 8)

    for (int s = 0; s < NSTEP; ++s) {
        int rp = s & 1, wp = rp ^ 1;

        const f16* a1; int s1;
        if (s < TSEQ) { a1 = (const f16*)xh + (size_t)s * IDIM; s1 = TSEQ * IDIM; }
        else          { a1 = (const f16*)fb; s1 = IDIM; }

        gemm_lstm<<<gL, 256, SMEM_MAIN>>>(
            a1, s1, 1,
            H1[rp], HDIM, 16,
            (const f16*)wih1, IDIM,
            (const f16*)whh1, HDIM,
            (const float*)bias1,
            (float*)c1, H1[wp]);

        gemm_lstm<<<gL, 256, SMEM_MAIN>>>(
            H1[wp], HDIM, 16,
            H2[rp], HDIM, 16,
            (const f16*)wih2, HDIM,
            (const f16*)whh2, HDIM,
            (const float*)bias2,
            (float*)c2, H2[wp]);

        lin_stage1_kernel<<<dim3(BSZ / 64, 8), 256>>>(H2[wp], W_lin);
        lin_stage2_kernel<<<(BSZ * IDIM) / 256, 256>>>(b_lin, out + (size_t)s * IDIM);
    }
}